// round 6
// baseline (speedup 1.0000x reference)
#include <cuda_runtime.h>
#include <cuda_bf16.h>

// ---------------------------------------------------------------------------
// DCAELiteMLA: x[4,512,64,64] ->
//   qkv  = conv1x1(x, w_qkv)                          [4,1536,4096]  tf32 MMA
//   agg  = grouped_pw1x1(depthwise5x5(qkv, pad=2))    [4,1536,4096]  fused
//   cat  = [qkv ; agg] -> 128 heads x 24 ch           (never materialized)
//   linear attention (DIM=8, ones-padded v row)       -> attn [4,1024,4096]
//   out  = x + conv1x1(attn, w_proj)                  [4,512,4096]   tf32 MMA
// ---------------------------------------------------------------------------

#define NB    4
#define HW    4096
#define C_IN  512
#define C_QKV 1536
#define C_ATT 1024
#define NHEAD 128

// Scratch (device globals: no allocation allowed in kernel_launch)
__device__ float g_qkv [NB * C_QKV * HW];   // ~100 MB
__device__ float g_agg [NB * C_QKV * HW];   // ~100 MB
__device__ float g_vk  [NB * NHEAD * 72];
__device__ float g_attn[NB * C_ATT * HW];   // ~67 MB

// ---------------------------------------------------------------------------
// tf32 tensor-core GEMM: C[b] = A * B[b] (+ Res[b])
// A: MxK row-major (weights), B: KxN row-major, C: MxN row-major.
// Block tile 128x128x16, 256 thr = 8 warps (4x2), warp tile 32x64
// = 2x8 mma.m16n8k8 fragments. Double-buffered smem (single sync/tile),
// register prefetch, vectorized STS.128 staging. M%128==0, N%128==0, K%16==0.
// ---------------------------------------------------------------------------
#define SA_STR 20    // As[m][k] stride (16 + 4 pad)  -> conflict-free frags
#define SB_STR 136   // Bs[k][n] stride (128 + 8 pad) -> conflict-free frags

__device__ __forceinline__ unsigned f2tf(float x) {
    unsigned r;
    asm("cvt.rna.tf32.f32 %0, %1;" : "=r"(r) : "f"(x));
    return r;
}

__device__ __forceinline__ float4 f2tf4(float4 v) {
    return make_float4(__uint_as_float(f2tf(v.x)), __uint_as_float(f2tf(v.y)),
                       __uint_as_float(f2tf(v.z)), __uint_as_float(f2tf(v.w)));
}

template <bool RES>
__global__ __launch_bounds__(256) void gemm_tf32(
    int M, int N, int K,
    const float* __restrict__ A,
    const float* __restrict__ B,
    float* __restrict__ C,
    const float* __restrict__ Res)
{
    const int bx = blockIdx.x, by = blockIdx.y, b = blockIdx.z;
    B += (size_t)b * K * N;
    C += (size_t)b * M * N;
    if (RES) Res += (size_t)b * M * N;

    __shared__ float sA[2][128 * SA_STR];
    __shared__ float sB[2][16 * SB_STR];

    const int tid  = threadIdx.x;
    const int wid  = tid >> 5;
    const int lane = tid & 31;
    const int gid  = lane >> 2;   // group id 0..7
    const int tig  = lane & 3;    // thread in group 0..3
    const int wRow = wid >> 1;    // 0..3 -> m offset *32
    const int wCol = wid & 1;     // 0..1 -> n offset *64

    // staging maps: A tile 128x16 (512 f4), B tile 16x128 (512 f4)
    const int aR0 = tid >> 2,          aC0 = (tid & 3) * 4;
    const int aR1 = (tid + 256) >> 2,  aC1 = aC0;
    const int bR0 = tid >> 5,          bC0 = (tid & 31) * 4;
    const int bR1 = bR0 + 8,           bC1 = bC0;

    const float* Ag0 = A + (size_t)(by * 128 + aR0) * K + aC0;
    const float* Ag1 = A + (size_t)(by * 128 + aR1) * K + aC1;
    const float* Bg0 = B + (size_t)bR0 * N + bx * 128 + bC0;
    const float* Bg1 = B + (size_t)bR1 * N + bx * 128 + bC1;

    // smem staging destinations (16B aligned: 80r+16c and 544r+16c bytes)
    const int sa0 = aR0 * SA_STR + aC0, sa1 = aR1 * SA_STR + aC1;
    const int sb0 = bR0 * SB_STR + bC0, sb1 = bR1 * SB_STR + bC1;

    float acc[2][8][4];
    #pragma unroll
    for (int i = 0; i < 2; i++)
        #pragma unroll
        for (int j = 0; j < 8; j++)
            #pragma unroll
            for (int q = 0; q < 4; q++) acc[i][j][q] = 0.f;

    float4 ra0, ra1, rb0, rb1;

    // prologue: tile 0 -> buf 0
    ra0 = *reinterpret_cast<const float4*>(Ag0);
    ra1 = *reinterpret_cast<const float4*>(Ag1);
    rb0 = *reinterpret_cast<const float4*>(Bg0);
    rb1 = *reinterpret_cast<const float4*>(Bg1);
    *reinterpret_cast<float4*>(&sA[0][sa0]) = f2tf4(ra0);
    *reinterpret_cast<float4*>(&sA[0][sa1]) = f2tf4(ra1);
    *reinterpret_cast<float4*>(&sB[0][sb0]) = f2tf4(rb0);
    *reinterpret_cast<float4*>(&sB[0][sb1]) = f2tf4(rb1);
    __syncthreads();

    const int kTiles = K >> 4;
    int buf = 0;

    for (int t = 0; t < kTiles; t++) {
        const bool more = (t + 1) < kTiles;
        if (more) {
            const int kt = (t + 1) << 4;
            ra0 = *reinterpret_cast<const float4*>(Ag0 + kt);
            ra1 = *reinterpret_cast<const float4*>(Ag1 + kt);
            rb0 = *reinterpret_cast<const float4*>(Bg0 + (size_t)kt * N);
            rb1 = *reinterpret_cast<const float4*>(Bg1 + (size_t)kt * N);
        }

        const float* a  = sA[buf];
        const float* bs = sB[buf];
        #pragma unroll
        for (int ks = 0; ks < 2; ks++) {
            const int k0 = ks * 8;
            unsigned af[2][4], bfr[8][2];
            #pragma unroll
            for (int mt = 0; mt < 2; mt++) {
                const int r = wRow * 32 + mt * 16 + gid;
                af[mt][0] = __float_as_uint(a[(r    ) * SA_STR + k0 + tig    ]);
                af[mt][1] = __float_as_uint(a[(r + 8) * SA_STR + k0 + tig    ]);
                af[mt][2] = __float_as_uint(a[(r    ) * SA_STR + k0 + tig + 4]);
                af[mt][3] = __float_as_uint(a[(r + 8) * SA_STR + k0 + tig + 4]);
            }
            #pragma unroll
            for (int nt = 0; nt < 8; nt++) {
                const int n = wCol * 64 + nt * 8 + gid;
                bfr[nt][0] = __float_as_uint(bs[(k0 + tig    ) * SB_STR + n]);
                bfr[nt][1] = __float_as_uint(bs[(k0 + tig + 4) * SB_STR + n]);
            }
            #pragma unroll
            for (int mt = 0; mt < 2; mt++)
                #pragma unroll
                for (int nt = 0; nt < 8; nt++) {
                    float* c = acc[mt][nt];
                    asm volatile(
                        "mma.sync.aligned.m16n8k8.row.col.f32.tf32.tf32.f32 "
                        "{%0,%1,%2,%3}, {%4,%5,%6,%7}, {%8,%9}, {%0,%1,%2,%3};"
                        : "+f"(c[0]), "+f"(c[1]), "+f"(c[2]), "+f"(c[3])
                        : "r"(af[mt][0]), "r"(af[mt][1]), "r"(af[mt][2]),
                          "r"(af[mt][3]), "r"(bfr[nt][0]), "r"(bfr[nt][1]));
                }
        }

        if (more) {
            // Single sync per tile: the buffer we write next (buf^1) was last
            // read in iteration t-1, and every thread passed the barrier at
            // the end of iteration t-1's staging before compute(t) began, so
            // writes below cannot race those reads. Compute(t) never touches
            // buf^1. Only the writer->reader barrier (below) is required.
            buf ^= 1;
            *reinterpret_cast<float4*>(&sA[buf][sa0]) = f2tf4(ra0);
            *reinterpret_cast<float4*>(&sA[buf][sa1]) = f2tf4(ra1);
            *reinterpret_cast<float4*>(&sB[buf][sb0]) = f2tf4(rb0);
            *reinterpret_cast<float4*>(&sB[buf][sb1]) = f2tf4(rb1);
            __syncthreads();
        }
    }

    // writeback: c0,c1 -> (row, 2*tig), c2,c3 -> (row+8, 2*tig)
    #pragma unroll
    for (int mt = 0; mt < 2; mt++) {
        const int r0 = by * 128 + wRow * 32 + mt * 16 + gid;
        #pragma unroll
        for (int nt = 0; nt < 8; nt++) {
            const int col = bx * 128 + wCol * 64 + nt * 8 + 2 * tig;
            const float* c = acc[mt][nt];
            size_t o0 = (size_t)r0 * N + col;
            size_t o1 = (size_t)(r0 + 8) * N + col;
            float2 v0 = make_float2(c[0], c[1]);
            float2 v1 = make_float2(c[2], c[3]);
            if (RES) {
                float2 q0 = *reinterpret_cast<const float2*>(Res + o0);
                float2 q1 = *reinterpret_cast<const float2*>(Res + o1);
                v0.x += q0.x; v0.y += q0.y;
                v1.x += q1.x; v1.y += q1.y;
            }
            *reinterpret_cast<float2*>(C + o0) = v0;
            *reinterpret_cast<float2*>(C + o1) = v1;
        }
    }
}

// ---------------------------------------------------------------------------
// FUSED depthwise 5x5 (pad=2) + grouped 1x1 (8-in -> 8-out).
// Block = (64,8) threads handles one (group, 8-row tile, batch).
// ---------------------------------------------------------------------------
__global__ __launch_bounds__(512) void dwpw_fused(
    const float* __restrict__ in, const float* __restrict__ wdw,
    const float* __restrict__ wpw, float* __restrict__ out)
{
    const int rt = blockIdx.x;      // 0..7 (row tile)
    const int g  = blockIdx.y;      // 0..191 (group)
    const int b  = blockIdx.z;

    __shared__ float s[8][12][68];
    __shared__ float wd[8][25];
    __shared__ float wp[64];

    const int tx = threadIdx.x, ty = threadIdx.y;
    const int t  = ty * 64 + tx;

    if (t < 200) wd[t / 25][t % 25] = wdw[g * 200 + t];
    else if (t < 264) wp[t - 200] = wpw[g * 64 + (t - 200)];

    const float* base = in + ((size_t)b * C_QKV + g * 8) * HW;
    const int r0 = rt * 8 - 2;

    for (int idx = t; idx < 8 * 12 * 68; idx += 512) {
        const int c  = idx / (12 * 68);
        const int r  = (idx / 68) % 12;
        const int lc = idx % 68;
        const int gr = r0 + r, gc = lc - 2;
        float v = 0.f;
        if (gr >= 0 && gr < 64 && gc >= 0 && gc < 64)
            v = base[(size_t)c * HW + gr * 64 + gc];
        s[c][r][lc] = v;
    }
    __syncthreads();

    float dw[8];
    #pragma unroll
    for (int c = 0; c < 8; c++) {
        float a = 0.f;
        #pragma unroll
        for (int dy = 0; dy < 5; dy++)
            #pragma unroll
            for (int dx = 0; dx < 5; dx++)
                a += s[c][ty + dy][tx + dx] * wd[c][dy * 5 + dx];
        dw[c] = a;
    }

    float* op = out + ((size_t)b * C_QKV + g * 8) * HW + (rt * 8 + ty) * 64 + tx;
    #pragma unroll
    for (int o = 0; o < 8; o++) {
        float a = 0.f;
        #pragma unroll
        for (int c = 0; c < 8; c++) a += wp[o * 8 + c] * dw[c];
        op[(size_t)o * HW] = a;
    }
}

// Head -> source channel base. Heads 0..63 read qkv, 64..127 read agg.
__device__ __forceinline__ const float* head_src(
    const float* qkv, const float* agg, int b, int h)
{
    return (h < 64) ? qkv + ((size_t)b * C_QKV + h * 24) * HW
                    : agg + ((size_t)b * C_QKV + (h - 64) * 24) * HW;
}

// ---------------------------------------------------------------------------
// Attention pass 1: vk[b,h,d(9),e(8)] = sum_n v[d,n] * relu(k[e,n]),
// v[8,n] = 1 (ones-pad row). One block per (h,b), 256 threads, float4 loads.
// ---------------------------------------------------------------------------
__global__ __launch_bounds__(256) void attn_vk(
    const float* __restrict__ qkv, const float* __restrict__ agg,
    float* __restrict__ vkout)
{
    const int h = blockIdx.x;
    const int b = blockIdx.y;
    const float* src = head_src(qkv, agg, b, h);

    float acc[72];
    #pragma unroll
    for (int i = 0; i < 72; i++) acc[i] = 0.f;

    // 1024 float4 columns, 256 threads -> 4 iterations
    for (int n4 = threadIdx.x; n4 < HW / 4; n4 += 256) {
        float4 kk[8], vv[8];
        #pragma unroll
        for (int e = 0; e < 8; e++) {
            float4 v = *reinterpret_cast<const float4*>(src + (size_t)(8 + e) * HW + n4 * 4);
            kk[e] = make_float4(fmaxf(v.x, 0.f), fmaxf(v.y, 0.f),
                                fmaxf(v.z, 0.f), fmaxf(v.w, 0.f));
        }
        #pragma unroll
        for (int d = 0; d < 8; d++)
            vv[d] = *reinterpret_cast<const float4*>(src + (size_t)(16 + d) * HW + n4 * 4);
        #pragma unroll
        for (int d = 0; d < 8; d++)
            #pragma unroll
            for (int e = 0; e < 8; e++)
                acc[d * 8 + e] += vv[d].x * kk[e].x + vv[d].y * kk[e].y
                                + vv[d].z * kk[e].z + vv[d].w * kk[e].w;
        #pragma unroll
        for (int e = 0; e < 8; e++)
            acc[64 + e] += kk[e].x + kk[e].y + kk[e].z + kk[e].w;
    }

    __shared__ float red[72];
    if (threadIdx.x < 72) red[threadIdx.x] = 0.f;
    __syncthreads();
    const int lane = threadIdx.x & 31;
    #pragma unroll
    for (int i = 0; i < 72; i++) {
        float v = acc[i];
        #pragma unroll
        for (int o = 16; o > 0; o >>= 1) v += __shfl_down_sync(0xffffffffu, v, o);
        if (lane == 0) atomicAdd(&red[i], v);
    }
    __syncthreads();
    if (threadIdx.x < 72)
        vkout[((size_t)b * NHEAD + h) * 72 + threadIdx.x] = red[threadIdx.x];
}

// ---------------------------------------------------------------------------
// Attention pass 2: out[d,n] = (sum_e vk[d,e]*q[e,n]) / (sum_e vk[8,e]*q[e,n]+eps)
// float4 over pixels: one thread handles 4 consecutive n.
// ---------------------------------------------------------------------------
__global__ __launch_bounds__(256) void attn_apply(
    const float* __restrict__ qkv, const float* __restrict__ agg,
    const float* __restrict__ vk, float* __restrict__ out)
{
    const int h = blockIdx.y;
    const int b = blockIdx.z;
    const int n4 = blockIdx.x * 256 + threadIdx.x;   // 0..1023
    const float* src = head_src(qkv, agg, b, h);

    __shared__ float s[72];
    if (threadIdx.x < 72)
        s[threadIdx.x] = vk[((size_t)b * NHEAD + h) * 72 + threadIdx.x];
    __syncthreads();

    float4 q[8];
    #pragma unroll
    for (int e = 0; e < 8; e++) {
        float4 v = *reinterpret_cast<const float4*>(src + (size_t)e * HW + n4 * 4);
        q[e] = make_float4(fmaxf(v.x, 0.f), fmaxf(v.y, 0.f),
                           fmaxf(v.z, 0.f), fmaxf(v.w, 0.f));
    }

    float4 den = make_float4(0.f, 0.f, 0.f, 0.f);
    #pragma unroll
    for (int e = 0; e < 8; e++) {
        den.x += s[64 + e] * q[e].x;
        den.y += s[64 + e] * q[e].y;
        den.z += s[64 + e] * q[e].z;
        den.w += s[64 + e] * q[e].w;
    }
    const float4 inv = make_float4(1.f / (den.x + 1e-15f), 1.f / (den.y + 1e-15f),
                                   1.f / (den.z + 1e-15f), 1.f / (den.w + 1e-15f));

    float* op = out + ((size_t)b * C_ATT + h * 8) * HW + n4 * 4;
    #pragma unroll
    for (int d = 0; d < 8; d++) {
        float4 num = make_float4(0.f, 0.f, 0.f, 0.f);
        #pragma unroll
        for (int e = 0; e < 8; e++) {
            const float w = s[d * 8 + e];
            num.x += w * q[e].x;
            num.y += w * q[e].y;
            num.z += w * q[e].z;
            num.w += w * q[e].w;
        }
        num.x *= inv.x; num.y *= inv.y; num.z *= inv.z; num.w *= inv.w;
        *reinterpret_cast<float4*>(op + (size_t)d * HW) = num;
    }
}

// ---------------------------------------------------------------------------
extern "C" void kernel_launch(void* const* d_in, const int* in_sizes, int n_in,
                              void* d_out, int out_size)
{
    const float* x      = (const float*)d_in[0];
    const float* w_qkv  = (const float*)d_in[1];
    const float* w_dw   = (const float*)d_in[2];
    const float* w_pw   = (const float*)d_in[3];
    const float* w_proj = (const float*)d_in[4];
    float* out = (float*)d_out;

    float *qkv, *agg, *vk, *attn;
    cudaGetSymbolAddress((void**)&qkv,  g_qkv);
    cudaGetSymbolAddress((void**)&agg,  g_agg);
    cudaGetSymbolAddress((void**)&vk,   g_vk);
    cudaGetSymbolAddress((void**)&attn, g_attn);

    // 1) qkv = w_qkv @ x           (M=1536, K=512, N=4096, per batch)
    gemm_tf32<false><<<dim3(HW / 128, C_QKV / 128, NB), 256>>>(
        C_QKV, HW, C_IN, w_qkv, x, qkv, nullptr);

    // 2+3) fused depthwise 5x5 + grouped pointwise
    dwpw_fused<<<dim3(8, 192, NB), dim3(64, 8)>>>(qkv, w_dw, w_pw, agg);

    // 4) linear attention
    attn_vk<<<dim3(NHEAD, NB), 256>>>(qkv, agg, vk);
    attn_apply<<<dim3(HW / 4 / 256, NHEAD, NB), 256>>>(qkv, agg, vk, attn);

    // 5) out = x + w_proj @ attn   (M=512, K=1024, N=4096, per batch)
    gemm_tf32<true><<<dim3(HW / 128, C_IN / 128, NB), 256>>>(
        C_IN, HW, C_ATT, w_proj, attn, out, x);
}